// round 5
// baseline (speedup 1.0000x reference)
#include <cuda_runtime.h>
#include <cstdint>

// ---------------- problem constants ----------------
#define BB 2
#define TT 2048
#define DD 1024
#define LL 4
#define VV 32000
#define HH 4096
#define BT (BB*TT)         // 4096

// ---------------- scratch (device globals; no allocation) ----------------
__device__ float g_x  [BT*DD];
__device__ float g_xr [BT*DD];
__device__ float g_h  [BT*DD];
__device__ float g_hr [BT*DD];
__device__ float g_q  [BT*DD];
__device__ float g_k  [BT*DD];
__device__ float g_v  [BT*DD];
__device__ float g_att[(size_t)BB*TT*TT];
__device__ float g_ff [(size_t)BT*HH];
// tf32-rounded weights (original orientation)
__device__ float g_wq [LL*DD*DD];
__device__ float g_wk [LL*DD*DD];
__device__ float g_wv [LL*DD*DD];
__device__ float g_w1 [(size_t)LL*DD*HH];
__device__ float g_w2 [(size_t)LL*HH*DD];
__device__ float g_pw [(size_t)DD*VV];

__device__ __forceinline__ float tf32r(float x) {
    uint32_t u = __float_as_uint(x), r;
    asm("cvt.rna.tf32.f32 %0, %1;" : "=r"(r) : "r"(u));
    return __uint_as_float(r);
}

// ---------------- weight rounding prepass ----------------
__global__ void round_kernel(const float* __restrict__ src, float* __restrict__ dst, int n4)
{
    int i = blockIdx.x * blockDim.x + threadIdx.x;
    if (i < n4) {
        float4 v = ((const float4*)src)[i];
        v.x = tf32r(v.x); v.y = tf32r(v.y); v.z = tf32r(v.z); v.w = tf32r(v.w);
        ((float4*)dst)[i] = v;
    }
}

// ---------------- embed ----------------
__global__ void embed_kernel(const int* __restrict__ tokens,
                             const float* __restrict__ emb,
                             const float* __restrict__ pos)
{
    int row = blockIdx.x;
    int t   = row % TT;
    int tok = tokens[row];
    const float4* e = (const float4*)(emb + (size_t)tok * DD);
    const float4* p = (const float4*)(pos + (size_t)t   * DD);
    float4*       o = (float4*)(g_x + (size_t)row * DD);
    for (int j = threadIdx.x; j < DD/4; j += blockDim.x) {
        float4 a = e[j], b = p[j];
        o[j] = make_float4(a.x+b.x, a.y+b.y, a.z+b.z, a.w+b.w);
    }
}

// ---------------- layernorm: full (out) + tf32-rounded (outr) ----------------
__global__ void ln_kernel(const float* __restrict__ in, float* __restrict__ out,
                          float* __restrict__ outr,
                          const float* __restrict__ gam, const float* __restrict__ bet)
{
    int row = blockIdx.x;
    const float* x = in + (size_t)row * DD;
    float s = 0.f, s2 = 0.f;
    for (int j = threadIdx.x; j < DD; j += 256) {
        float v = x[j]; s += v; s2 += v*v;
    }
    #pragma unroll
    for (int o = 16; o; o >>= 1) {
        s  += __shfl_xor_sync(0xffffffffu, s,  o);
        s2 += __shfl_xor_sync(0xffffffffu, s2, o);
    }
    __shared__ float sb[16];
    int wid = threadIdx.x >> 5, lid = threadIdx.x & 31;
    if (lid == 0) { sb[wid] = s; sb[8+wid] = s2; }
    __syncthreads();
    s = 0.f; s2 = 0.f;
    #pragma unroll
    for (int w = 0; w < 8; w++) { s += sb[w]; s2 += sb[8+w]; }
    float mu  = s * (1.f/DD);
    float var = s2 * (1.f/DD) - mu*mu;
    float r   = rsqrtf(var + 1e-5f);
    float* y  = out  + (size_t)row * DD;
    float* yr = outr + (size_t)row * DD;
    for (int j = threadIdx.x; j < DD; j += 256) {
        float v = (x[j] - mu) * r * gam[j] + bet[j];
        y[j]  = v;
        yr[j] = tf32r(v);
    }
}

// ---------------- causal softmax (writes tf32-rounded probs; zeros masked) -----
__global__ void softmax_kernel(float* __restrict__ att)
{
    int t = blockIdx.x, b = blockIdx.y;
    float* row = att + ((size_t)b*TT + t) * (size_t)TT;
    int len = t + 1;
    int tid = threadIdx.x;
    __shared__ float sr[8];

    float mx = -1e30f;
    for (int j = tid; j < len; j += 256) mx = fmaxf(mx, row[j]);
    #pragma unroll
    for (int o = 16; o; o >>= 1) mx = fmaxf(mx, __shfl_xor_sync(0xffffffffu, mx, o));
    if ((tid & 31) == 0) sr[tid>>5] = mx;
    __syncthreads();
    mx = sr[0];
    #pragma unroll
    for (int w = 1; w < 8; w++) mx = fmaxf(mx, sr[w]);
    __syncthreads();

    float sum = 0.f;
    for (int j = tid; j < len; j += 256) {
        float e = __expf(row[j] - mx);
        row[j] = e; sum += e;
    }
    #pragma unroll
    for (int o = 16; o; o >>= 1) sum += __shfl_xor_sync(0xffffffffu, sum, o);
    if ((tid & 31) == 0) sr[tid>>5] = sum;
    __syncthreads();
    sum = 0.f;
    #pragma unroll
    for (int w = 0; w < 8; w++) sum += sr[w];
    float inv = __fdividef(1.f, sum);
    for (int j = tid; j < TT; j += 256)
        row[j] = (j < len) ? tf32r(row[j] * inv) : 0.f;
}

// ================= tf32 mma.sync GEMM, 128x256x32, 3-stage pipeline ============
// C = alpha*(A @ B(^T)) [+bias] [+res] [relu] [round] [aux rounded copy Cr]
// 256 threads = 8 warps (2m x 4n), warp tile 64x64. Inputs pre-rounded to tf32.
// CAUSAL: 0=none, 1=skip n0>m0+127 (QK^T), 2=clamp K at m0+128 (AV)

__device__ __forceinline__ void mma_tf32(float* d, const uint32_t* a, const uint32_t* b) {
    asm volatile("mma.sync.aligned.m16n8k8.row.col.f32.tf32.tf32.f32 "
        "{%0,%1,%2,%3}, {%4,%5,%6,%7}, {%8,%9}, {%0,%1,%2,%3};"
        : "+f"(d[0]), "+f"(d[1]), "+f"(d[2]), "+f"(d[3])
        : "r"(a[0]), "r"(a[1]), "r"(a[2]), "r"(a[3]), "r"(b[0]), "r"(b[1]));
}

__device__ __forceinline__ void cp16(void* dst, const void* src) {
    uint32_t d = (uint32_t)__cvta_generic_to_shared(dst);
    asm volatile("cp.async.cg.shared.global [%0], [%1], 16;" :: "r"(d), "l"(src));
}

template<bool TRANSB> struct GCfg {
    static constexpr int ASTR = 36;
    static constexpr int ASZ  = 128 * 36;
    static constexpr int BSTR = TRANSB ? 36 : 264;
    static constexpr int BSZ  = TRANSB ? 256 * 36 : 32 * 264;
    static constexpr int SMEM = 3 * (ASZ + BSZ) * 4;
};

template<bool TRANSB, bool RELU, int CAUSAL, bool ROUND>
__global__ void __launch_bounds__(256, 1)
gemm_tc(const float* __restrict__ A, const float* __restrict__ Bm,
        float* __restrict__ C, float* __restrict__ Cr,
        int M, int N, int K, float alpha,
        const float* __restrict__ bias, const float* __restrict__ res,
        long long strA, long long strB, long long strC)
{
    constexpr int ASZ  = GCfg<TRANSB>::ASZ;
    constexpr int BSZ  = GCfg<TRANSB>::BSZ;

    int m0 = blockIdx.y * 128, n0 = blockIdx.x * 256;
    if (CAUSAL == 1 && n0 > m0 + 127) return;
    int kEnd = (CAUSAL == 2) ? min(K, m0 + 128) : K;

    A  += (long long)blockIdx.z * strA;
    Bm += (long long)blockIdx.z * strB;
    C  += (long long)blockIdx.z * strC;
    const float* resp = res ? res + (long long)blockIdx.z * strC : (const float*)nullptr;
    float* Crp = Cr ? Cr + (long long)blockIdx.z * strC : (float*)nullptr;

    extern __shared__ float smf[];
    float* As = smf;
    float* Bs = smf + 3 * ASZ;

    int tid = threadIdx.x;

    auto load_stage = [&](int k0, int s) {
        float* Ad = As + s * ASZ;
        const float* Ag = A + (size_t)m0 * K + k0;
        #pragma unroll
        for (int i = 0; i < 4; i++) {
            int ch = tid + 256 * i;
            int r = ch >> 3, c = (ch & 7) << 2;          // 128 rows x 8 x 16B
            cp16(Ad + r * 36 + c, Ag + (size_t)r * K + c);
        }
        float* Bd = Bs + s * BSZ;
        if (TRANSB) {
            const float* Bg = Bm + (size_t)n0 * K + k0;
            #pragma unroll
            for (int i = 0; i < 8; i++) {
                int ch = tid + 256 * i;
                int r = ch >> 3, c = (ch & 7) << 2;      // 256 n-rows x 8 x 16B
                cp16(Bd + r * 36 + c, Bg + (size_t)r * K + c);
            }
        } else {
            const float* Bg = Bm + (size_t)k0 * N + n0;
            #pragma unroll
            for (int i = 0; i < 8; i++) {
                int ch = tid + 256 * i;
                int r = ch >> 6, c = (ch & 63) << 2;     // 32 k-rows x 64 x 16B
                cp16(Bd + r * 264 + c, Bg + (size_t)r * N + c);
            }
        }
        asm volatile("cp.async.commit_group;" ::: "memory");
    };

    int wid = tid >> 5, lane = tid & 31;
    int wm = wid & 1, wn = wid >> 1;       // 2 (M) x 4 (N)
    int g = lane >> 2, tg = lane & 3;

    float acc[4][8][4];
    #pragma unroll
    for (int i = 0; i < 4; i++)
        #pragma unroll
        for (int j = 0; j < 8; j++)
            #pragma unroll
            for (int r = 0; r < 4; r++) acc[i][j][r] = 0.f;

    int nIter = kEnd / 32;
    int issued = 0;
    #pragma unroll 1
    for (int p = 0; p < 2 && p < nIter; p++) { load_stage(p * 32, p); issued++; }

    #pragma unroll 1
    for (int it = 0; it < nIter; it++) {
        if (issued - it > 1) asm volatile("cp.async.wait_group 1;" ::: "memory");
        else                 asm volatile("cp.async.wait_group 0;" ::: "memory");
        __syncthreads();

        if (issued < nIter) { load_stage(issued * 32, issued % 3); issued++; }

        const uint32_t* At = (const uint32_t*)(As + (it % 3) * ASZ);
        const uint32_t* Bt = (const uint32_t*)(Bs + (it % 3) * BSZ);

        #pragma unroll
        for (int kt = 0; kt < 4; kt++) {
            int kk = kt * 8 + tg;
            uint32_t af[4][4], bf[8][2];
            #pragma unroll
            for (int i = 0; i < 4; i++) {
                int r = wm * 64 + i * 16 + g;
                af[i][0] = At[r * 36 + kk];
                af[i][1] = At[(r + 8) * 36 + kk];
                af[i][2] = At[r * 36 + kk + 4];
                af[i][3] = At[(r + 8) * 36 + kk + 4];
            }
            #pragma unroll
            for (int j = 0; j < 8; j++) {
                int n = wn * 64 + j * 8 + g;
                if (TRANSB) {
                    bf[j][0] = Bt[n * 36 + kk];
                    bf[j][1] = Bt[n * 36 + kk + 4];
                } else {
                    bf[j][0] = Bt[kk * 264 + n];
                    bf[j][1] = Bt[(kk + 4) * 264 + n];
                }
            }
            #pragma unroll
            for (int i = 0; i < 4; i++)
                #pragma unroll
                for (int j = 0; j < 8; j++)
                    mma_tf32(acc[i][j], af[i], bf[j]);
        }
    }

    __syncthreads();

    // epilogue
    #pragma unroll
    for (int i = 0; i < 4; i++) {
        #pragma unroll
        for (int j = 0; j < 8; j++) {
            int m = m0 + wm * 64 + i * 16 + g;
            int n = n0 + wn * 64 + j * 8 + 2 * tg;
            float c00 = acc[i][j][0] * alpha, c01 = acc[i][j][1] * alpha;
            float c10 = acc[i][j][2] * alpha, c11 = acc[i][j][3] * alpha;
            if (bias) {
                float b0 = bias[n], b1 = bias[n + 1];
                c00 += b0; c01 += b1; c10 += b0; c11 += b1;
            }
            if (resp) {
                float2 r0 = *(const float2*)(resp + (size_t)m * N + n);
                float2 r1 = *(const float2*)(resp + (size_t)(m + 8) * N + n);
                c00 += r0.x; c01 += r0.y; c10 += r1.x; c11 += r1.y;
            }
            if (RELU) {
                c00 = fmaxf(c00, 0.f); c01 = fmaxf(c01, 0.f);
                c10 = fmaxf(c10, 0.f); c11 = fmaxf(c11, 0.f);
            }
            if (ROUND) {
                c00 = tf32r(c00); c01 = tf32r(c01);
                c10 = tf32r(c10); c11 = tf32r(c11);
            }
            *(float2*)(C + (size_t)m * N + n)       = make_float2(c00, c01);
            *(float2*)(C + (size_t)(m + 8) * N + n) = make_float2(c10, c11);
            if (Crp) {
                *(float2*)(Crp + (size_t)m * N + n) =
                    make_float2(tf32r(c00), tf32r(c01));
                *(float2*)(Crp + (size_t)(m + 8) * N + n) =
                    make_float2(tf32r(c10), tf32r(c11));
            }
        }
    }
}

// ---------------- host orchestration ----------------
static inline float* sym(const void* s)
{
    void* p = nullptr;
    cudaGetSymbolAddress(&p, s);
    return (float*)p;
}

extern "C" void kernel_launch(void* const* d_in, const int* in_sizes, int n_in,
                              void* d_out, int out_size)
{
    const int*   tokens = (const int*)  d_in[0];
    const float* emb    = (const float*)d_in[1];
    const float* pos    = (const float*)d_in[2];
    const float* Wq     = (const float*)d_in[3];
    const float* Wk     = (const float*)d_in[4];
    const float* Wv     = (const float*)d_in[5];
    const float* w1     = (const float*)d_in[6];
    const float* b1     = (const float*)d_in[7];
    const float* w2     = (const float*)d_in[8];
    const float* b2     = (const float*)d_in[9];
    const float* g1     = (const float*)d_in[10];
    const float* bln1   = (const float*)d_in[11];
    const float* g2     = (const float*)d_in[12];
    const float* bln2   = (const float*)d_in[13];
    const float* projw  = (const float*)d_in[14];
    const float* projb  = (const float*)d_in[15];
    float* out = (float*)d_out;

    float* x   = sym(g_x);
    float* xr  = sym(g_xr);
    float* h   = sym(g_h);
    float* hr  = sym(g_hr);
    float* q   = sym(g_q);
    float* k   = sym(g_k);
    float* v   = sym(g_v);
    float* att = sym(g_att);
    float* ff  = sym(g_ff);
    float* wqr = sym(g_wq);
    float* wkr = sym(g_wk);
    float* wvr = sym(g_wv);
    float* w1r = sym(g_w1);
    float* w2r = sym(g_w2);
    float* pwr = sym(g_pw);

    constexpr int SM_N  = GCfg<false>::SMEM;   // 156672
    constexpr int SM_T  = GCfg<true >::SMEM;   // 165888

    cudaFuncSetAttribute(gemm_tc<false,false,0,true >, cudaFuncAttributeMaxDynamicSharedMemorySize, SM_N);
    cudaFuncSetAttribute(gemm_tc<true, false,1,false>, cudaFuncAttributeMaxDynamicSharedMemorySize, SM_T);
    cudaFuncSetAttribute(gemm_tc<false,false,2,false>, cudaFuncAttributeMaxDynamicSharedMemorySize, SM_N);
    cudaFuncSetAttribute(gemm_tc<false,true, 0,true >, cudaFuncAttributeMaxDynamicSharedMemorySize, SM_N);
    cudaFuncSetAttribute(gemm_tc<false,false,0,false>, cudaFuncAttributeMaxDynamicSharedMemorySize, SM_N);

    // ---- weight rounding prepass ----
    {
        int n;
        n = LL*DD*DD/4;
        round_kernel<<<(n+255)/256, 256>>>(Wq, wqr, n);
        round_kernel<<<(n+255)/256, 256>>>(Wk, wkr, n);
        round_kernel<<<(n+255)/256, 256>>>(Wv, wvr, n);
        n = LL*DD*HH/4;
        round_kernel<<<(n+255)/256, 256>>>(w1, w1r, n);
        round_kernel<<<(n+255)/256, 256>>>(w2, w2r, n);
        n = DD*VV/4;
        round_kernel<<<(n+255)/256, 256>>>(projw, pwr, n);
    }

    const float attn_scale = 1.0f / 32.0f;

    embed_kernel<<<BT, 256>>>(tokens, emb, pos);

    for (int l = 0; l < LL; l++) {
        ln_kernel<<<BT, 256>>>(x, h, hr, g1 + l*DD, bln1 + l*DD);

        dim3 gq(DD/256, BT/128);
        gemm_tc<false,false,0,true><<<gq, 256, SM_N>>>(hr, wqr + (size_t)l*DD*DD, q, nullptr,
            BT, DD, DD, 1.f, nullptr, nullptr, 0, 0, 0);
        gemm_tc<false,false,0,true><<<gq, 256, SM_N>>>(hr, wkr + (size_t)l*DD*DD, k, nullptr,
            BT, DD, DD, 1.f, nullptr, nullptr, 0, 0, 0);
        gemm_tc<false,false,0,true><<<gq, 256, SM_N>>>(hr, wvr + (size_t)l*DD*DD, v, nullptr,
            BT, DD, DD, 1.f, nullptr, nullptr, 0, 0, 0);

        // att = scale * q @ k^T (batched, causal tile-skip)
        dim3 ga(TT/256, TT/128, BB);
        gemm_tc<true,false,1,false><<<ga, 256, SM_T>>>(q, k, att, nullptr,
            TT, TT, DD, attn_scale, nullptr, nullptr,
            (long long)TT*DD, (long long)TT*DD, (long long)TT*TT);

        softmax_kernel<<<dim3(TT, BB), 256>>>(att);

        // x = att @ v + x (batched, K clamped at diagonal)
        dim3 gv(DD/256, TT/128, BB);
        gemm_tc<false,false,2,false><<<gv, 256, SM_N>>>(att, v, x, nullptr,
            TT, DD, TT, 1.f, nullptr, x,
            (long long)TT*TT, (long long)TT*DD, (long long)TT*DD);

        ln_kernel<<<BT, 256>>>(x, h, hr, g2 + l*DD, bln2 + l*DD);

        // ff = relu(y @ w1 + b1), rounded
        dim3 g1d(HH/256, BT/128);
        gemm_tc<false,true,0,true><<<g1d, 256, SM_N>>>(hr, w1r + (size_t)l*DD*HH, ff, nullptr,
            BT, HH, DD, 1.f, b1 + (size_t)l*HH, nullptr, 0, 0, 0);

        // x = ff @ w2 + b2 + y (full) ; xr = rounded copy
        dim3 g2d(DD/256, BT/128);
        gemm_tc<false,false,0,false><<<g2d, 256, SM_N>>>(ff, w2r + (size_t)l*HH*DD, x, xr,
            BT, DD, HH, 1.f, b2 + (size_t)l*DD, h, 0, 0, 0);
    }

    // logits = xr @ proj_w + projb
    dim3 gp(VV/256, BT/128);
    gemm_tc<false,false,0,false><<<gp, 256, SM_N>>>(xr, pwr, out, nullptr,
        BT, VV, DD, 1.f, projb, nullptr, 0, 0, 0);
}

// round 6
// speedup vs baseline: 1.6086x; 1.6086x over previous
#include <cuda_runtime.h>
#include <cuda_fp16.h>
#include <cstdint>

// ---------------- problem constants ----------------
#define BB 2
#define TT 2048
#define DD 1024
#define LL 4
#define VV 32000
#define HH 4096
#define BT (BB*TT)         // 4096

// ---------------- scratch (device globals; no allocation) ----------------
__device__ float  g_x  [BT*DD];                    // residual stream fp32
__device__ float  g_h  [BT*DD];                    // LN output fp32 (FFN residual)
__device__ float  g_att[(size_t)BB*TT*TT];         // QK^T logits fp32
__device__ __half g_hr [BT*DD];                    // LN output fp16
__device__ __half g_xh [BT*DD];                    // x fp16 (final proj input)
__device__ __half g_q  [BT*DD];
__device__ __half g_k  [BT*DD];
__device__ __half g_vT [(size_t)BB*DD*TT];         // v transposed [B][D][T]
__device__ __half g_ah [(size_t)BB*TT*TT];         // softmax probs fp16
__device__ __half g_ff [(size_t)BT*HH];
// transposed fp16 weights, all [N][K] K-major
__device__ __half g_wqT[(size_t)LL*DD*DD];
__device__ __half g_wkT[(size_t)LL*DD*DD];
__device__ __half g_wvT[(size_t)LL*DD*DD];
__device__ __half g_w1T[(size_t)LL*HH*DD];
__device__ __half g_w2T[(size_t)LL*DD*HH];
__device__ __half g_pwT[(size_t)VV*DD];

// ---------------- transpose + fp16 convert prepass ----------------
// src [z][R][C] fp32 -> dst [z][C][R] fp16
__global__ void transpose_cvt(const float* __restrict__ src, __half* __restrict__ dst,
                              int R, int C, long long sStr, long long dStr)
{
    __shared__ float t[32][33];
    src += (long long)blockIdx.z * sStr;
    dst += (long long)blockIdx.z * dStr;
    int c0 = blockIdx.x * 32, r0 = blockIdx.y * 32;
    #pragma unroll
    for (int i = 0; i < 32; i += 8)
        t[threadIdx.y + i][threadIdx.x] =
            src[(size_t)(r0 + threadIdx.y + i) * C + c0 + threadIdx.x];
    __syncthreads();
    #pragma unroll
    for (int i = 0; i < 32; i += 8)
        dst[(size_t)(c0 + threadIdx.y + i) * R + r0 + threadIdx.x] =
            __float2half_rn(t[threadIdx.x][threadIdx.y + i]);
}

// ---------------- embed ----------------
__global__ void embed_kernel(const int* __restrict__ tokens,
                             const float* __restrict__ emb,
                             const float* __restrict__ pos)
{
    int row = blockIdx.x;
    int t   = row % TT;
    int tok = tokens[row];
    const float4* e = (const float4*)(emb + (size_t)tok * DD);
    const float4* p = (const float4*)(pos + (size_t)t   * DD);
    float4*       o = (float4*)(g_x + (size_t)row * DD);
    for (int j = threadIdx.x; j < DD/4; j += blockDim.x) {
        float4 a = e[j], b = p[j];
        o[j] = make_float4(a.x+b.x, a.y+b.y, a.z+b.z, a.w+b.w);
    }
}

// ---------------- layernorm: full fp32 (out) + fp16 (outr) ----------------
__global__ void ln_kernel(const float* __restrict__ in, float* __restrict__ out,
                          __half* __restrict__ outr,
                          const float* __restrict__ gam, const float* __restrict__ bet)
{
    int row = blockIdx.x;
    const float* x = in + (size_t)row * DD;
    float s = 0.f, s2 = 0.f;
    for (int j = threadIdx.x; j < DD; j += 256) {
        float v = x[j]; s += v; s2 += v*v;
    }
    #pragma unroll
    for (int o = 16; o; o >>= 1) {
        s  += __shfl_xor_sync(0xffffffffu, s,  o);
        s2 += __shfl_xor_sync(0xffffffffu, s2, o);
    }
    __shared__ float sb[16];
    int wid = threadIdx.x >> 5, lid = threadIdx.x & 31;
    if (lid == 0) { sb[wid] = s; sb[8+wid] = s2; }
    __syncthreads();
    s = 0.f; s2 = 0.f;
    #pragma unroll
    for (int w = 0; w < 8; w++) { s += sb[w]; s2 += sb[8+w]; }
    float mu  = s * (1.f/DD);
    float var = s2 * (1.f/DD) - mu*mu;
    float r   = rsqrtf(var + 1e-5f);
    float*  y  = out  + (size_t)row * DD;
    __half* yr = outr + (size_t)row * DD;
    for (int j = threadIdx.x; j < DD; j += 256) {
        float v = (x[j] - mu) * r * gam[j] + bet[j];
        y[j]  = v;
        yr[j] = __float2half_rn(v);
    }
}

// ---------------- causal softmax: fp32 logits -> fp16 probs (zeros masked) -----
__global__ void softmax_kernel(const float* __restrict__ att, __half* __restrict__ atth)
{
    int t = blockIdx.x, b = blockIdx.y;
    const float* row = att  + ((size_t)b*TT + t) * (size_t)TT;
    __half*      orow = atth + ((size_t)b*TT + t) * (size_t)TT;
    int len = t + 1;
    int tid = threadIdx.x;
    __shared__ float sr[8];

    float mx = -1e30f;
    for (int j = tid; j < len; j += 256) mx = fmaxf(mx, row[j]);
    #pragma unroll
    for (int o = 16; o; o >>= 1) mx = fmaxf(mx, __shfl_xor_sync(0xffffffffu, mx, o));
    if ((tid & 31) == 0) sr[tid>>5] = mx;
    __syncthreads();
    mx = sr[0];
    #pragma unroll
    for (int w = 1; w < 8; w++) mx = fmaxf(mx, sr[w]);
    __syncthreads();

    float sum = 0.f;
    for (int j = tid; j < len; j += 256) sum += __expf(row[j] - mx);
    #pragma unroll
    for (int o = 16; o; o >>= 1) sum += __shfl_xor_sync(0xffffffffu, sum, o);
    if ((tid & 31) == 0) sr[tid>>5] = sum;
    __syncthreads();
    sum = 0.f;
    #pragma unroll
    for (int w = 0; w < 8; w++) sum += sr[w];
    float inv = __fdividef(1.f, sum);
    for (int j = tid; j < TT; j += 256)
        orow[j] = (j < len) ? __float2half_rn(__expf(row[j] - mx) * inv)
                            : __float2half_rn(0.f);
}

// ================= fp16 mma.sync GEMM (TN), 128x128x32, 3-stage ================
// C[m][n] = alpha * sum_k A[m][k]*B[n][k] (+bias[n]) (+res) (relu)
// OUT: 0 = fp32 C32, 1 = fp16 C16, 2 = both.
// CAUSAL: 0=none, 1=skip tile if n0>m0+127, 2=clamp K at m0+128.
// 256 threads = 8 warps (2m x 4n), warp tile 64x32, mma m16n8k16 f32.f16.f16.f32.
// smem rows: 32 halves = 16 u32 data + 4 pad => stride 20 u32 (conflict-free).

__device__ __forceinline__ void mma_f16(float* d, const uint32_t* a, const uint32_t* b) {
    asm volatile("mma.sync.aligned.m16n8k16.row.col.f32.f16.f16.f32 "
        "{%0,%1,%2,%3}, {%4,%5,%6,%7}, {%8,%9}, {%0,%1,%2,%3};"
        : "+f"(d[0]), "+f"(d[1]), "+f"(d[2]), "+f"(d[3])
        : "r"(a[0]), "r"(a[1]), "r"(a[2]), "r"(a[3]), "r"(b[0]), "r"(b[1]));
}

__device__ __forceinline__ void cp16(void* dst, const void* src) {
    uint32_t d = (uint32_t)__cvta_generic_to_shared(dst);
    asm volatile("cp.async.cg.shared.global [%0], [%1], 16;" :: "r"(d), "l"(src));
}

#define STG_U32 2560                 // 128 rows * 20 u32
#define HSMEM   (6 * STG_U32 * 4)    // 3 stages * (A+B) = 61440 B

template<int CAUSAL, int OUT, bool RELU>
__global__ void __launch_bounds__(256, 2)
hgemm(const __half* __restrict__ A, long long strA, int lda,
      const __half* __restrict__ Bm, long long strB, int ldb,
      float* __restrict__ C32, __half* __restrict__ C16, long long strC, int ldc,
      int K, float alpha,
      const float* __restrict__ bias, const float* __restrict__ res)
{
    int m0 = blockIdx.y * 128, n0 = blockIdx.x * 128;
    if (CAUSAL == 1 && n0 > m0 + 127) return;
    int kEnd = (CAUSAL == 2) ? min(K, m0 + 128) : K;

    A  += (long long)blockIdx.z * strA;
    Bm += (long long)blockIdx.z * strB;
    const float* resp = res ? res + (long long)blockIdx.z * strC : (const float*)nullptr;
    float*  Co = (OUT != 1) ? C32 + (long long)blockIdx.z * strC : (float*)nullptr;
    __half* Ch = (OUT != 0) ? C16 + (long long)blockIdx.z * strC : (__half*)nullptr;

    extern __shared__ uint32_t sm32[];
    uint32_t* As = sm32;
    uint32_t* Bs = sm32 + 3 * STG_U32;

    int tid = threadIdx.x;

    auto load_stage = [&](int k0, int s) {
        uint32_t* Ad = As + s * STG_U32;
        const __half* Ag = A + (size_t)m0 * lda + k0;
        #pragma unroll
        for (int i = 0; i < 2; i++) {
            int ch = tid + 256 * i;
            int r = ch >> 2, c = ch & 3;                  // 128 rows x 4 x 16B
            cp16(Ad + r * 20 + c * 4, Ag + (size_t)r * lda + c * 8);
        }
        uint32_t* Bd = Bs + s * STG_U32;
        const __half* Bg = Bm + (size_t)n0 * ldb + k0;
        #pragma unroll
        for (int i = 0; i < 2; i++) {
            int ch = tid + 256 * i;
            int r = ch >> 2, c = ch & 3;
            cp16(Bd + r * 20 + c * 4, Bg + (size_t)r * ldb + c * 8);
        }
        asm volatile("cp.async.commit_group;" ::: "memory");
    };

    int wid = tid >> 5, lane = tid & 31;
    int wm = wid & 1, wn = wid >> 1;      // 2 (M) x 4 (N)
    int g = lane >> 2, tg = lane & 3;

    float acc[4][4][4];
    #pragma unroll
    for (int i = 0; i < 4; i++)
        #pragma unroll
        for (int j = 0; j < 4; j++)
            #pragma unroll
            for (int r = 0; r < 4; r++) acc[i][j][r] = 0.f;

    int nIter = kEnd / 32;
    int issued = 0;
    #pragma unroll 1
    for (int p = 0; p < 2 && p < nIter; p++) { load_stage(p * 32, p); issued++; }

    #pragma unroll 1
    for (int it = 0; it < nIter; it++) {
        if (issued - it > 1) asm volatile("cp.async.wait_group 1;" ::: "memory");
        else                 asm volatile("cp.async.wait_group 0;" ::: "memory");
        __syncthreads();

        if (issued < nIter) { load_stage(issued * 32, issued % 3); issued++; }

        const uint32_t* At = As + (it % 3) * STG_U32;
        const uint32_t* Bt = Bs + (it % 3) * STG_U32;

        #pragma unroll
        for (int kt = 0; kt < 2; kt++) {
            int kc = kt * 8 + tg;
            uint32_t af[4][4], bf[4][2];
            #pragma unroll
            for (int i = 0; i < 4; i++) {
                int r = wm * 64 + i * 16 + g;
                af[i][0] = At[r * 20 + kc];
                af[i][1] = At[(r + 8) * 20 + kc];
                af[i][2] = At[r * 20 + kc + 4];
                af[i][3] = At[(r + 8) * 20 + kc + 4];
            }
            #pragma unroll
            for (int j = 0; j < 4; j++) {
                int n = wn * 32 + j * 8 + g;
                bf[j][0] = Bt[n * 20 + kc];
                bf[j][1] = Bt[n * 20 + kc + 4];
            }
            #pragma unroll
            for (int i = 0; i < 4; i++)
                #pragma unroll
                for (int j = 0; j < 4; j++)
                    mma_f16(acc[i][j], af[i], bf[j]);
        }
    }

    __syncthreads();

    // epilogue
    #pragma unroll
    for (int i = 0; i < 4; i++) {
        #pragma unroll
        for (int j = 0; j < 4; j++) {
            int m = m0 + wm * 64 + i * 16 + g;
            int n = n0 + wn * 32 + j * 8 + 2 * tg;
            float c00 = acc[i][j][0] * alpha, c01 = acc[i][j][1] * alpha;
            float c10 = acc[i][j][2] * alpha, c11 = acc[i][j][3] * alpha;
            if (bias) {
                float b0 = bias[n], b1 = bias[n + 1];
                c00 += b0; c01 += b1; c10 += b0; c11 += b1;
            }
            if (resp) {
                float2 r0 = *(const float2*)(resp + (size_t)m * ldc + n);
                float2 r1 = *(const float2*)(resp + (size_t)(m + 8) * ldc + n);
                c00 += r0.x; c01 += r0.y; c10 += r1.x; c11 += r1.y;
            }
            if (RELU) {
                c00 = fmaxf(c00, 0.f); c01 = fmaxf(c01, 0.f);
                c10 = fmaxf(c10, 0.f); c11 = fmaxf(c11, 0.f);
            }
            if (OUT != 1) {
                *(float2*)(Co + (size_t)m * ldc + n)       = make_float2(c00, c01);
                *(float2*)(Co + (size_t)(m + 8) * ldc + n) = make_float2(c10, c11);
            }
            if (OUT != 0) {
                *(__half2*)(Ch + (size_t)m * ldc + n)       = __floats2half2_rn(c00, c01);
                *(__half2*)(Ch + (size_t)(m + 8) * ldc + n) = __floats2half2_rn(c10, c11);
            }
        }
    }
}

// ---------------- host orchestration ----------------
template<typename T>
static inline T* sym(const void* s)
{
    void* p = nullptr;
    cudaGetSymbolAddress(&p, s);
    return (T*)p;
}

extern "C" void kernel_launch(void* const* d_in, const int* in_sizes, int n_in,
                              void* d_out, int out_size)
{
    const int*   tokens = (const int*)  d_in[0];
    const float* emb    = (const float*)d_in[1];
    const float* pos    = (const float*)d_in[2];
    const float* Wq     = (const float*)d_in[3];
    const float* Wk     = (const float*)d_in[4];
    const float* Wv     = (const float*)d_in[5];
    const float* w1     = (const float*)d_in[6];
    const float* b1     = (const float*)d_in[7];
    const float* w2     = (const float*)d_in[8];
    const float* b2     = (const float*)d_in[9];
    const float* g1     = (const float*)d_in[10];
    const float* bln1   = (const float*)d_in[11];
    const float* g2     = (const float*)d_in[12];
    const float* bln2   = (const float*)d_in[13];
    const float* projw  = (const float*)d_in[14];
    const float* projb  = (const float*)d_in[15];
    float* out = (float*)d_out;

    float*  x   = sym<float >(g_x);
    float*  h   = sym<float >(g_h);
    float*  att = sym<float >(g_att);
    __half* hr  = sym<__half>(g_hr);
    __half* xh  = sym<__half>(g_xh);
    __half* q   = sym<__half>(g_q);
    __half* k   = sym<__half>(g_k);
    __half* vT  = sym<__half>(g_vT);
    __half* ah  = sym<__half>(g_ah);
    __half* ff  = sym<__half>(g_ff);
    __half* wqT = sym<__half>(g_wqT);
    __half* wkT = sym<__half>(g_wkT);
    __half* wvT = sym<__half>(g_wvT);
    __half* w1T = sym<__half>(g_w1T);
    __half* w2T = sym<__half>(g_w2T);
    __half* pwT = sym<__half>(g_pwT);

    cudaFuncSetAttribute(hgemm<0,1,false>, cudaFuncAttributeMaxDynamicSharedMemorySize, HSMEM);
    cudaFuncSetAttribute(hgemm<0,1,true >, cudaFuncAttributeMaxDynamicSharedMemorySize, HSMEM);
    cudaFuncSetAttribute(hgemm<0,2,false>, cudaFuncAttributeMaxDynamicSharedMemorySize, HSMEM);
    cudaFuncSetAttribute(hgemm<0,0,false>, cudaFuncAttributeMaxDynamicSharedMemorySize, HSMEM);
    cudaFuncSetAttribute(hgemm<1,0,false>, cudaFuncAttributeMaxDynamicSharedMemorySize, HSMEM);
    cudaFuncSetAttribute(hgemm<2,0,false>, cudaFuncAttributeMaxDynamicSharedMemorySize, HSMEM);

    // ---- weight transpose + fp16 convert prepass ----
    dim3 tb(32, 8);
    transpose_cvt<<<dim3(DD/32, DD/32, LL), tb>>>(Wq, wqT, DD, DD, (long long)DD*DD, (long long)DD*DD);
    transpose_cvt<<<dim3(DD/32, DD/32, LL), tb>>>(Wk, wkT, DD, DD, (long long)DD*DD, (long long)DD*DD);
    transpose_cvt<<<dim3(DD/32, DD/32, LL), tb>>>(Wv, wvT, DD, DD, (long long)DD*DD, (long long)DD*DD);
    transpose_cvt<<<dim3(HH/32, DD/32, LL), tb>>>(w1, w1T, DD, HH, (long long)DD*HH, (long long)DD*HH);
    transpose_cvt<<<dim3(DD/32, HH/32, LL), tb>>>(w2, w2T, HH, DD, (long long)HH*DD, (long long)HH*DD);
    transpose_cvt<<<dim3(VV/32, DD/32, 1 ), tb>>>(projw, pwT, DD, VV, 0, 0);

    const float attn_scale = 1.0f / 32.0f;

    embed_kernel<<<BT, 256>>>(tokens, emb, pos);

    for (int l = 0; l < LL; l++) {
        ln_kernel<<<BT, 256>>>(x, h, hr, g1 + l*DD, bln1 + l*DD);

        // q,k = hr @ W^T   [4096x1024]x[1024x1024] -> fp16
        dim3 gq(DD/128, BT/128);
        hgemm<0,1,false><<<gq, 256, HSMEM>>>(hr, 0, DD, wqT + (size_t)l*DD*DD, 0, DD,
            nullptr, q, 0, DD, DD, 1.f, nullptr, nullptr);
        hgemm<0,1,false><<<gq, 256, HSMEM>>>(hr, 0, DD, wkT + (size_t)l*DD*DD, 0, DD,
            nullptr, k, 0, DD, DD, 1.f, nullptr, nullptr);

        // vT[b][d][t] = sum_k WvT[d][k]*hr[b,t][k]  -> fp16 [B][D][T]
        dim3 gvt(TT/128, DD/128, BB);
        hgemm<0,1,false><<<gvt, 256, HSMEM>>>(wvT + (size_t)l*DD*DD, 0, DD,
            hr, (long long)TT*DD, DD,
            nullptr, vT, (long long)DD*TT, TT, DD, 1.f, nullptr, nullptr);

        // att = scale * q @ k^T (fp32 logits, causal tile-skip)
        dim3 ga(TT/128, TT/128, BB);
        hgemm<1,0,false><<<ga, 256, HSMEM>>>(q, (long long)TT*DD, DD, k, (long long)TT*DD, DD,
            att, nullptr, (long long)TT*TT, TT, DD, attn_scale, nullptr, nullptr);

        softmax_kernel<<<dim3(TT, BB), 256>>>(att, ah);

        // x += ah @ vT^T (K clamped at diagonal)
        dim3 gav(DD/128, TT/128, BB);
        hgemm<2,0,false><<<gav, 256, HSMEM>>>(ah, (long long)TT*TT, TT, vT, (long long)DD*TT, TT,
            x, nullptr, (long long)TT*DD, DD, TT, 1.f, nullptr, x);

        ln_kernel<<<BT, 256>>>(x, h, hr, g2 + l*DD, bln2 + l*DD);

        // ff = relu(hr @ w1^T + b1) -> fp16
        dim3 gf1(HH/128, BT/128);
        hgemm<0,1,true><<<gf1, 256, HSMEM>>>(hr, 0, DD, w1T + (size_t)l*HH*DD, 0, DD,
            nullptr, ff, 0, HH, DD, 1.f, b1 + (size_t)l*HH, nullptr);

        // x = ff @ w2^T + b2 + h (fp32) ; xh = fp16 copy
        dim3 gf2(DD/128, BT/128);
        hgemm<0,2,false><<<gf2, 256, HSMEM>>>(ff, 0, HH, w2T + (size_t)l*DD*HH, 0, HH,
            x, xh, 0, DD, HH, 1.f, b2 + (size_t)l*DD, h);
    }

    // logits = xh @ pwT^T + projb  (fp32 out)
    dim3 gp(VV/128, BT/128);
    hgemm<0,0,false><<<gp, 256, HSMEM>>>(xh, 0, DD, pwT, 0, DD,
        out, nullptr, 0, VV, DD, 1.f, projb, nullptr);
}

// round 7
// speedup vs baseline: 1.8501x; 1.1502x over previous
#include <cuda_runtime.h>
#include <cuda_fp16.h>
#include <cstdint>

// ---------------- problem constants ----------------
#define BB 2
#define TT 2048
#define DD 1024
#define LL 4
#define VV 32000
#define HH 4096
#define BT (BB*TT)         // 4096

// ---------------- scratch (device globals; no allocation) ----------------
__device__ float  g_x  [BT*DD];                    // residual stream fp32
__device__ float  g_h  [BT*DD];                    // LN output fp32 (FFN residual)
__device__ float  g_att[(size_t)BB*TT*TT];         // QK^T logits fp32
__device__ __half g_hr [BT*DD];                    // LN output fp16
__device__ __half g_xh [BT*DD];                    // x fp16 (final proj input)
__device__ __half g_qk [(size_t)BT*2*DD];          // q|k packed [BT][2D]
__device__ __half g_vT [(size_t)BB*DD*TT];         // v transposed [B][D][T]
__device__ __half g_ah [(size_t)BB*TT*TT];         // softmax probs fp16
__device__ __half g_ff [(size_t)BT*HH];
// transposed fp16 weights, K-major
__device__ __half g_wqkT[(size_t)LL*2*DD*DD];      // Wq^T | Wk^T packed [2D][D]
__device__ __half g_wvT [(size_t)LL*DD*DD];
__device__ __half g_w1T [(size_t)LL*HH*DD];
__device__ __half g_w2T [(size_t)LL*DD*HH];
__device__ __half g_pwT [(size_t)VV*DD];

// ---------------- transpose + fp16 convert prepass ----------------
__global__ void transpose_cvt(const float* __restrict__ src, __half* __restrict__ dst,
                              int R, int C, long long sStr, long long dStr)
{
    __shared__ float t[32][33];
    src += (long long)blockIdx.z * sStr;
    dst += (long long)blockIdx.z * dStr;
    int c0 = blockIdx.x * 32, r0 = blockIdx.y * 32;
    #pragma unroll
    for (int i = 0; i < 32; i += 8)
        t[threadIdx.y + i][threadIdx.x] =
            src[(size_t)(r0 + threadIdx.y + i) * C + c0 + threadIdx.x];
    __syncthreads();
    #pragma unroll
    for (int i = 0; i < 32; i += 8)
        dst[(size_t)(c0 + threadIdx.y + i) * R + r0 + threadIdx.x] =
            __float2half_rn(t[threadIdx.x][threadIdx.y + i]);
}

// ---------------- embed ----------------
__global__ void embed_kernel(const int* __restrict__ tokens,
                             const float* __restrict__ emb,
                             const float* __restrict__ pos)
{
    int row = blockIdx.x;
    int t   = row % TT;
    int tok = tokens[row];
    const float4* e = (const float4*)(emb + (size_t)tok * DD);
    const float4* p = (const float4*)(pos + (size_t)t   * DD);
    float4*       o = (float4*)(g_x + (size_t)row * DD);
    for (int j = threadIdx.x; j < DD/4; j += blockDim.x) {
        float4 a = e[j], b = p[j];
        o[j] = make_float4(a.x+b.x, a.y+b.y, a.z+b.z, a.w+b.w);
    }
}

// ---------------- layernorm: fp32 (out) + fp16 (outr) ----------------
__global__ void ln_kernel(const float* __restrict__ in, float* __restrict__ out,
                          __half* __restrict__ outr,
                          const float* __restrict__ gam, const float* __restrict__ bet)
{
    int row = blockIdx.x;
    const float* x = in + (size_t)row * DD;
    float s = 0.f, s2 = 0.f;
    for (int j = threadIdx.x; j < DD; j += 256) {
        float v = x[j]; s += v; s2 += v*v;
    }
    #pragma unroll
    for (int o = 16; o; o >>= 1) {
        s  += __shfl_xor_sync(0xffffffffu, s,  o);
        s2 += __shfl_xor_sync(0xffffffffu, s2, o);
    }
    __shared__ float sb[16];
    int wid = threadIdx.x >> 5, lid = threadIdx.x & 31;
    if (lid == 0) { sb[wid] = s; sb[8+wid] = s2; }
    __syncthreads();
    s = 0.f; s2 = 0.f;
    #pragma unroll
    for (int w = 0; w < 8; w++) { s += sb[w]; s2 += sb[8+w]; }
    float mu  = s * (1.f/DD);
    float var = s2 * (1.f/DD) - mu*mu;
    float r   = rsqrtf(var + 1e-5f);
    float*  y  = out  + (size_t)row * DD;
    __half* yr = outr + (size_t)row * DD;
    for (int j = threadIdx.x; j < DD; j += 256) {
        float v = (x[j] - mu) * r * gam[j] + bet[j];
        y[j]  = v;
        yr[j] = __float2half_rn(v);
    }
}

// ---------------- causal softmax: fp32 logits -> fp16 probs ----------------
__global__ void softmax_kernel(const float* __restrict__ att, __half* __restrict__ atth)
{
    int t = blockIdx.x, b = blockIdx.y;
    const float* row  = att  + ((size_t)b*TT + t) * (size_t)TT;
    __half*      orow = atth + ((size_t)b*TT + t) * (size_t)TT;
    int len = t + 1;
    int tid = threadIdx.x;
    __shared__ float sr[8];

    float mx = -1e30f;
    for (int j = tid; j < len; j += 256) mx = fmaxf(mx, row[j]);
    #pragma unroll
    for (int o = 16; o; o >>= 1) mx = fmaxf(mx, __shfl_xor_sync(0xffffffffu, mx, o));
    if ((tid & 31) == 0) sr[tid>>5] = mx;
    __syncthreads();
    mx = sr[0];
    #pragma unroll
    for (int w = 1; w < 8; w++) mx = fmaxf(mx, sr[w]);
    __syncthreads();

    float sum = 0.f;
    for (int j = tid; j < len; j += 256) sum += __expf(row[j] - mx);
    #pragma unroll
    for (int o = 16; o; o >>= 1) sum += __shfl_xor_sync(0xffffffffu, sum, o);
    if ((tid & 31) == 0) sr[tid>>5] = sum;
    __syncthreads();
    sum = 0.f;
    #pragma unroll
    for (int w = 0; w < 8; w++) sum += sr[w];
    float inv = __fdividef(1.f, sum);
    for (int j = tid; j < TT; j += 256)
        orow[j] = (j < len) ? __float2half_rn(__expf(row[j] - mx) * inv)
                            : __float2half_rn(0.f);
}

// ============ fp16 mma.sync GEMM (TN), 128x128x32, 4-stage, ldmatrix ============
// C[m][n] = alpha * sum_k A[m][k]*B[n][k] (+bias[n]) (+res) (relu)
// OUT: 0 = fp32, 1 = fp16, 2 = both. CAUSAL: 0=none, 1=tile-skip, 2=K-clamp.
// 256 threads = 8 warps (2m x 4n), warp tile 64x32.
// smem row = 32 halves (16 u32) + 4 u32 pad -> stride 20 u32 (ldmatrix conflict-free).

__device__ __forceinline__ void mma_f16(float* d, const uint32_t* a, const uint32_t* b) {
    asm volatile("mma.sync.aligned.m16n8k16.row.col.f32.f16.f16.f32 "
        "{%0,%1,%2,%3}, {%4,%5,%6,%7}, {%8,%9}, {%0,%1,%2,%3};"
        : "+f"(d[0]), "+f"(d[1]), "+f"(d[2]), "+f"(d[3])
        : "r"(a[0]), "r"(a[1]), "r"(a[2]), "r"(a[3]), "r"(b[0]), "r"(b[1]));
}
__device__ __forceinline__ void ldm_x4(uint32_t* r, uint32_t saddr) {
    asm volatile("ldmatrix.sync.aligned.m8n8.x4.shared.b16 {%0,%1,%2,%3}, [%4];"
        : "=r"(r[0]), "=r"(r[1]), "=r"(r[2]), "=r"(r[3]) : "r"(saddr));
}
__device__ __forceinline__ void cp16(void* dst, const void* src) {
    uint32_t d = (uint32_t)__cvta_generic_to_shared(dst);
    asm volatile("cp.async.cg.shared.global [%0], [%1], 16;" :: "r"(d), "l"(src));
}

#define STG_U32 2560                  // 128 rows * 20 u32
#define NSTAGE  4
#define HSMEM   (2 * NSTAGE * STG_U32 * 4)   // 81920 B

template<int CAUSAL, int OUT, bool RELU>
__global__ void __launch_bounds__(256, 2)
hgemm(const __half* __restrict__ A, long long strA, int lda,
      const __half* __restrict__ Bm, long long strB, int ldb,
      float* __restrict__ C32, __half* __restrict__ C16, long long strC, int ldc,
      int K, float alpha,
      const float* __restrict__ bias, const float* __restrict__ res)
{
    int m0 = blockIdx.y * 128, n0 = blockIdx.x * 128;
    if (CAUSAL == 1 && n0 > m0 + 127) return;
    int kEnd = (CAUSAL == 2) ? min(K, m0 + 128) : K;

    A  += (long long)blockIdx.z * strA;
    Bm += (long long)blockIdx.z * strB;
    const float* resp = res ? res + (long long)blockIdx.z * strC : (const float*)nullptr;
    float*  Co = (OUT != 1) ? C32 + (long long)blockIdx.z * strC : (float*)nullptr;
    __half* Ch = (OUT != 0) ? C16 + (long long)blockIdx.z * strC : (__half*)nullptr;

    extern __shared__ uint32_t sm32[];
    uint32_t* As = sm32;                         // stages 0..3
    uint32_t* Bs = sm32 + NSTAGE * STG_U32;      // stages 0..3
    uint32_t smb = (uint32_t)__cvta_generic_to_shared(sm32);

    int tid = threadIdx.x;

    auto load_stage = [&](int k0, int s) {
        uint32_t* Ad = As + s * STG_U32;
        const __half* Ag = A + (size_t)m0 * lda + k0;
        #pragma unroll
        for (int i = 0; i < 2; i++) {
            int ch = tid + 256 * i;
            int r = ch >> 2, c = ch & 3;
            cp16(Ad + r * 20 + c * 4, Ag + (size_t)r * lda + c * 8);
        }
        uint32_t* Bd = Bs + s * STG_U32;
        const __half* Bg = Bm + (size_t)n0 * ldb + k0;
        #pragma unroll
        for (int i = 0; i < 2; i++) {
            int ch = tid + 256 * i;
            int r = ch >> 2, c = ch & 3;
            cp16(Bd + r * 20 + c * 4, Bg + (size_t)r * ldb + c * 8);
        }
        asm volatile("cp.async.commit_group;" ::: "memory");
    };

    int wid = tid >> 5, lane = tid & 31;
    int wm = wid & 1, wn = wid >> 1;      // 2 (M) x 4 (N)
    int g = lane >> 2, tg = lane & 3;

    // ldmatrix per-thread addressing (u32 offsets within a stage)
    int arow = wm * 64 + (lane & 15);            // + i*16
    int aoff = (lane >> 4) << 2;                 // k half-select (+4 u32)
    int nrow = wn * 32 + ((lane >> 4) << 3) + (lane & 7);   // + p*16
    int boff = ((lane >> 3) & 1) << 2;

    float acc[4][4][4];
    #pragma unroll
    for (int i = 0; i < 4; i++)
        #pragma unroll
        for (int j = 0; j < 4; j++)
            #pragma unroll
            for (int r = 0; r < 4; r++) acc[i][j][r] = 0.f;

    int nIter = kEnd / 32;
    int issued = 0;
    #pragma unroll 1
    for (int p = 0; p < 3 && p < nIter; p++) { load_stage(p * 32, p); issued++; }

    #pragma unroll 1
    for (int it = 0; it < nIter; it++) {
        int ahead = issued - it;
        if (ahead >= 3)      asm volatile("cp.async.wait_group 2;" ::: "memory");
        else if (ahead == 2) asm volatile("cp.async.wait_group 1;" ::: "memory");
        else                 asm volatile("cp.async.wait_group 0;" ::: "memory");
        __syncthreads();

        if (issued < nIter) { load_stage(issued * 32, issued & 3); issued++; }

        uint32_t AtA = smb + (((it & 3) * STG_U32) << 2);
        uint32_t BtA = smb + (((NSTAGE + (it & 3)) * STG_U32) << 2);

        #pragma unroll
        for (int kt = 0; kt < 2; kt++) {
            uint32_t af[4][4], bf[4][2];
            #pragma unroll
            for (int i = 0; i < 4; i++)
                ldm_x4(af[i], AtA + (((arow + i * 16) * 20 + kt * 8 + aoff) << 2));
            #pragma unroll
            for (int p = 0; p < 2; p++) {
                uint32_t t[4];
                ldm_x4(t, BtA + (((nrow + p * 16) * 20 + kt * 8 + boff) << 2));
                bf[2*p][0] = t[0]; bf[2*p][1] = t[1];
                bf[2*p+1][0] = t[2]; bf[2*p+1][1] = t[3];
            }
            #pragma unroll
            for (int i = 0; i < 4; i++)
                #pragma unroll
                for (int j = 0; j < 4; j++)
                    mma_f16(acc[i][j], af[i], bf[j]);
        }
    }

    __syncthreads();

    // epilogue
    #pragma unroll
    for (int i = 0; i < 4; i++) {
        #pragma unroll
        for (int j = 0; j < 4; j++) {
            int m = m0 + wm * 64 + i * 16 + g;
            int n = n0 + wn * 32 + j * 8 + 2 * tg;
            float c00 = acc[i][j][0] * alpha, c01 = acc[i][j][1] * alpha;
            float c10 = acc[i][j][2] * alpha, c11 = acc[i][j][3] * alpha;
            if (bias) {
                float b0 = bias[n], b1 = bias[n + 1];
                c00 += b0; c01 += b1; c10 += b0; c11 += b1;
            }
            if (resp) {
                float2 r0 = *(const float2*)(resp + (size_t)m * ldc + n);
                float2 r1 = *(const float2*)(resp + (size_t)(m + 8) * ldc + n);
                c00 += r0.x; c01 += r0.y; c10 += r1.x; c11 += r1.y;
            }
            if (RELU) {
                c00 = fmaxf(c00, 0.f); c01 = fmaxf(c01, 0.f);
                c10 = fmaxf(c10, 0.f); c11 = fmaxf(c11, 0.f);
            }
            if (OUT != 1) {
                *(float2*)(Co + (size_t)m * ldc + n)       = make_float2(c00, c01);
                *(float2*)(Co + (size_t)(m + 8) * ldc + n) = make_float2(c10, c11);
            }
            if (OUT != 0) {
                *(__half2*)(Ch + (size_t)m * ldc + n)       = __floats2half2_rn(c00, c01);
                *(__half2*)(Ch + (size_t)(m + 8) * ldc + n) = __floats2half2_rn(c10, c11);
            }
        }
    }
}

// ---------------- host orchestration ----------------
template<typename T>
static inline T* sym(const void* s)
{
    void* p = nullptr;
    cudaGetSymbolAddress(&p, s);
    return (T*)p;
}

extern "C" void kernel_launch(void* const* d_in, const int* in_sizes, int n_in,
                              void* d_out, int out_size)
{
    const int*   tokens = (const int*)  d_in[0];
    const float* emb    = (const float*)d_in[1];
    const float* pos    = (const float*)d_in[2];
    const float* Wq     = (const float*)d_in[3];
    const float* Wk     = (const float*)d_in[4];
    const float* Wv     = (const float*)d_in[5];
    const float* w1     = (const float*)d_in[6];
    const float* b1     = (const float*)d_in[7];
    const float* w2     = (const float*)d_in[8];
    const float* b2     = (const float*)d_in[9];
    const float* g1     = (const float*)d_in[10];
    const float* bln1   = (const float*)d_in[11];
    const float* g2     = (const float*)d_in[12];
    const float* bln2   = (const float*)d_in[13];
    const float* projw  = (const float*)d_in[14];
    const float* projb  = (const float*)d_in[15];
    float* out = (float*)d_out;

    float*  x    = sym<float >(g_x);
    float*  h    = sym<float >(g_h);
    float*  att  = sym<float >(g_att);
    __half* hr   = sym<__half>(g_hr);
    __half* xh   = sym<__half>(g_xh);
    __half* qk   = sym<__half>(g_qk);
    __half* vT   = sym<__half>(g_vT);
    __half* ah   = sym<__half>(g_ah);
    __half* ff   = sym<__half>(g_ff);
    __half* wqkT = sym<__half>(g_wqkT);
    __half* wvT  = sym<__half>(g_wvT);
    __half* w1T  = sym<__half>(g_w1T);
    __half* w2T  = sym<__half>(g_w2T);
    __half* pwT  = sym<__half>(g_pwT);

    cudaFuncSetAttribute(hgemm<0,1,false>, cudaFuncAttributeMaxDynamicSharedMemorySize, HSMEM);
    cudaFuncSetAttribute(hgemm<0,1,true >, cudaFuncAttributeMaxDynamicSharedMemorySize, HSMEM);
    cudaFuncSetAttribute(hgemm<0,2,false>, cudaFuncAttributeMaxDynamicSharedMemorySize, HSMEM);
    cudaFuncSetAttribute(hgemm<0,0,false>, cudaFuncAttributeMaxDynamicSharedMemorySize, HSMEM);
    cudaFuncSetAttribute(hgemm<1,0,false>, cudaFuncAttributeMaxDynamicSharedMemorySize, HSMEM);
    cudaFuncSetAttribute(hgemm<2,0,false>, cudaFuncAttributeMaxDynamicSharedMemorySize, HSMEM);

    // ---- weight transpose + fp16 convert prepass ----
    dim3 tb(32, 8);
    // Wq -> rows [0,D) of wqkT[l], Wk -> rows [D,2D)
    transpose_cvt<<<dim3(DD/32, DD/32, LL), tb>>>(Wq, wqkT,      DD, DD, (long long)DD*DD, (long long)2*DD*DD);
    transpose_cvt<<<dim3(DD/32, DD/32, LL), tb>>>(Wk, wqkT+DD*DD,DD, DD, (long long)DD*DD, (long long)2*DD*DD);
    transpose_cvt<<<dim3(DD/32, DD/32, LL), tb>>>(Wv, wvT, DD, DD, (long long)DD*DD, (long long)DD*DD);
    transpose_cvt<<<dim3(HH/32, DD/32, LL), tb>>>(w1, w1T, DD, HH, (long long)DD*HH, (long long)DD*HH);
    transpose_cvt<<<dim3(DD/32, HH/32, LL), tb>>>(w2, w2T, HH, DD, (long long)HH*DD, (long long)HH*DD);
    transpose_cvt<<<dim3(VV/32, DD/32, 1 ), tb>>>(projw, pwT, DD, VV, 0, 0);

    const float attn_scale = 1.0f / 32.0f;

    embed_kernel<<<BT, 256>>>(tokens, emb, pos);

    for (int l = 0; l < LL; l++) {
        ln_kernel<<<BT, 256>>>(x, h, hr, g1 + l*DD, bln1 + l*DD);

        // qk = hr @ [Wq|Wk]^T   [4096x1024]x[1024x2048] -> fp16, ldc=2D
        dim3 gqk(2*DD/128, BT/128);
        hgemm<0,1,false><<<gqk, 256, HSMEM>>>(hr, 0, DD, wqkT + (size_t)l*2*DD*DD, 0, DD,
            nullptr, qk, 0, 2*DD, DD, 1.f, nullptr, nullptr);

        // vT[b][d][t] = sum_k WvT[d][k]*hr[b,t][k] -> fp16 [B][D][T]
        dim3 gvt(TT/128, DD/128, BB);
        hgemm<0,1,false><<<gvt, 256, HSMEM>>>(wvT + (size_t)l*DD*DD, 0, DD,
            hr, (long long)TT*DD, DD,
            nullptr, vT, (long long)DD*TT, TT, DD, 1.f, nullptr, nullptr);

        // att = scale * q @ k^T (q = qk cols [0,D), k = qk cols [D,2D))
        dim3 ga(TT/128, TT/128, BB);
        hgemm<1,0,false><<<ga, 256, HSMEM>>>(qk, (long long)TT*2*DD, 2*DD,
            qk + DD, (long long)TT*2*DD, 2*DD,
            att, nullptr, (long long)TT*TT, TT, DD, attn_scale, nullptr, nullptr);

        softmax_kernel<<<dim3(TT, BB), 256>>>(att, ah);

        // x += ah @ vT^T (K clamped at diagonal)
        dim3 gav(DD/128, TT/128, BB);
        hgemm<2,0,false><<<gav, 256, HSMEM>>>(ah, (long long)TT*TT, TT, vT, (long long)DD*TT, TT,
            x, nullptr, (long long)TT*DD, DD, TT, 1.f, nullptr, x);

        ln_kernel<<<BT, 256>>>(x, h, hr, g2 + l*DD, bln2 + l*DD);

        // ff = relu(hr @ w1^T + b1) -> fp16
        dim3 gf1(HH/128, BT/128);
        hgemm<0,1,true><<<gf1, 256, HSMEM>>>(hr, 0, DD, w1T + (size_t)l*HH*DD, 0, DD,
            nullptr, ff, 0, HH, DD, 1.f, b1 + (size_t)l*HH, nullptr);

        // x = ff @ w2^T + b2 + h (fp32) ; xh = fp16 copy
        dim3 gf2(DD/128, BT/128);
        hgemm<0,2,false><<<gf2, 256, HSMEM>>>(ff, 0, HH, w2T + (size_t)l*DD*HH, 0, HH,
            x, xh, 0, DD, HH, 1.f, b2 + (size_t)l*DD, h);
    }

    // logits = xh @ pwT^T + projb (fp32 out)
    dim3 gp(VV/128, BT/128);
    hgemm<0,0,false><<<gp, 256, HSMEM>>>(xh, 0, DD, pwT, 0, DD,
        out, nullptr, 0, VV, DD, 1.f, projb, nullptr);
}